// round 14
// baseline (speedup 1.0000x reference)
#include <cuda_runtime.h>
#include <cuda_bf16.h>
#include <cuda_fp16.h>
#include <cstdint>

#define N_NODES 100000
#define N_EDGES 1600000
#define DF      128
#define NTILES  782          // ceil(100000/128)

// ---------------- scratch (device globals: allocation-free) ----------------
// per-src row (fp16, interleaved): 32 groups of [q4 | v4] (8 halfs = 16B each).
// NOTE: q values are stored PRE-HALVED (q/2) so the tanh-sigmoid needs no mul.
static __device__ __half g_qvh[(size_t)N_NODES * 256];
// per-dst row (fp32): [k(128) | s(128)]
static __device__ float g_ks[(size_t)N_NODES * 256];
static __device__ int   g_rowptr[N_NODES + 1];
static __device__ int   g_fill[N_NODES];
static __device__ int   g_esrc[N_EDGES];
// bf16 hi/lo split operands (weights double-buffered: [layer][mat][n][k])
static __device__ __nv_bfloat16 g_ahi[(size_t)N_NODES * DF];
static __device__ __nv_bfloat16 g_alo[(size_t)N_NODES * DF];
static __device__ __nv_bfloat16 g_bthi[2 * 4 * 128 * 128];
static __device__ __nv_bfloat16 g_btlo[2 * 4 * 128 * 128];
// layer-3 scalars
static __device__ float g3k[N_NODES], g3q[N_NODES], g3v[N_NODES], g3s[N_NODES];

// ---------------- helpers ----------------
__device__ __forceinline__ uint32_t smem_u32(const void* p) {
    uint32_t a;
    asm("{ .reg .u64 t; cvta.to.shared.u64 t, %1; cvt.u32.u64 %0, t; }" : "=r"(a) : "l"(p));
    return a;
}

// XOR swizzle: tile is [128 rows][128 bf16] = row stride 256B, 16 chunks of 16B.
__device__ __forceinline__ uint32_t swz(int row, int chunk) {
    return (uint32_t)(row * 256 + ((chunk ^ (row & 7)) << 4));
}

#define LDSM_X4(r0, r1, r2, r3, addr) \
    asm volatile("ldmatrix.sync.aligned.m8n8.x4.shared.b16 {%0,%1,%2,%3}, [%4];" \
        : "=r"(r0), "=r"(r1), "=r"(r2), "=r"(r3) : "r"(addr))
#define LDSM_X2(r0, r1, addr) \
    asm volatile("ldmatrix.sync.aligned.m8n8.x2.shared.b16 {%0,%1}, [%2];" \
        : "=r"(r0), "=r"(r1) : "r"(addr))
#define MMA16816(d, a, b) \
    asm volatile("mma.sync.aligned.m16n8k16.row.col.f32.bf16.bf16.f32 " \
        "{%0,%1,%2,%3},{%4,%5,%6,%7},{%8,%9},{%0,%1,%2,%3};" \
        : "+f"((d)[0]), "+f"((d)[1]), "+f"((d)[2]), "+f"((d)[3]) \
        : "r"((a)[0]), "r"((a)[1]), "r"((a)[2]), "r"((a)[3]), "r"((b)[0]), "r"((b)[1]))

// exact sigmoid (final layer only)
__device__ __forceinline__ float fsig(float x) {
    return __fdividef(1.f, 1.f + __expf(-x));
}
// half-argument fast sigmoid: input y = x/2 already; sigma(x) = 0.5*tanh(y)+0.5
__device__ __forceinline__ float fsig_h(float y) {
    float t;
    asm("tanh.approx.f32 %0, %1;" : "=f"(t) : "f"(y));
    return fmaf(t, 0.5f, 0.5f);
}

// ---------------- CSR build ----------------
__global__ void zero_cnt_kernel() {
    int i = blockIdx.x * blockDim.x + threadIdx.x;
    if (i < N_NODES) g_fill[i] = 0;
}
__global__ void hist_kernel(const int* __restrict__ dst) {
    int e = blockIdx.x * blockDim.x + threadIdx.x;
    if (e < N_EDGES) atomicAdd(&g_fill[dst[e]], 1);
}
__global__ void scan_kernel() {
    __shared__ int wsum[32];
    __shared__ int carry;
    int tid = threadIdx.x, lane = tid & 31, wid = tid >> 5;
    if (tid == 0) carry = 0;
    __syncthreads();
    for (int base = 0; base < N_NODES; base += 4096) {
        int idx = base + tid * 4;
        int v0 = 0, v1 = 0, v2 = 0, v3 = 0;
        if (idx + 3 < N_NODES) {
            int4 t = *reinterpret_cast<const int4*>(g_fill + idx);
            v0 = t.x; v1 = t.y; v2 = t.z; v3 = t.w;
        } else {
            if (idx + 0 < N_NODES) v0 = g_fill[idx + 0];
            if (idx + 1 < N_NODES) v1 = g_fill[idx + 1];
            if (idx + 2 < N_NODES) v2 = g_fill[idx + 2];
            if (idx + 3 < N_NODES) v3 = g_fill[idx + 3];
        }
        int s0 = v0, s1 = s0 + v1, s2 = s1 + v2, s3 = s2 + v3;
        int x = s3;
#pragma unroll
        for (int o = 1; o < 32; o <<= 1) { int t = __shfl_up_sync(~0u, x, o); if (lane >= o) x += t; }
        if (lane == 31) wsum[wid] = x;
        __syncthreads();
        if (wid == 0) {
            int y = wsum[lane];
#pragma unroll
            for (int o = 1; o < 32; o <<= 1) { int t = __shfl_up_sync(~0u, y, o); if (lane >= o) y += t; }
            wsum[lane] = y;
        }
        __syncthreads();
        int excl = carry + (x - s3) + (wid ? wsum[wid - 1] : 0);
        int e0 = excl, e1 = excl + s0, e2 = excl + s1, e3 = excl + s2;
        if (idx + 0 < N_NODES) { g_rowptr[idx + 0] = e0; g_fill[idx + 0] = e0; }
        if (idx + 1 < N_NODES) { g_rowptr[idx + 1] = e1; g_fill[idx + 1] = e1; }
        if (idx + 2 < N_NODES) { g_rowptr[idx + 2] = e2; g_fill[idx + 2] = e2; }
        if (idx + 3 < N_NODES) { g_rowptr[idx + 3] = e3; g_fill[idx + 3] = e3; }
        __syncthreads();
        if (tid == 0) carry += wsum[31];
        __syncthreads();
    }
    if (tid == 0) g_rowptr[N_NODES] = N_EDGES;
}
__global__ void scatter_kernel(const int* __restrict__ src, const int* __restrict__ dst) {
    int e = blockIdx.x * blockDim.x + threadIdx.x;
    if (e < N_EDGES) {
        int d = dst[e];
        int p = atomicAdd(&g_fill[d], 1);
        g_esrc[p] = src[e];
    }
}

// ---------------- fp32 -> bf16 hi/lo conversion (layer-1 input only) ----------
__global__ void convx_kernel(const float* __restrict__ X) {
    int i = blockIdx.x * blockDim.x + threadIdx.x;
    if (i >= (N_NODES * DF) / 4) return;
    float4 v = *reinterpret_cast<const float4*>(X + (size_t)i * 4);
    __nv_bfloat16 h0 = __float2bfloat16(v.x), h1 = __float2bfloat16(v.y);
    __nv_bfloat16 h2 = __float2bfloat16(v.z), h3 = __float2bfloat16(v.w);
    __nv_bfloat16 l0 = __float2bfloat16(v.x - __bfloat162float(h0));
    __nv_bfloat16 l1 = __float2bfloat16(v.y - __bfloat162float(h1));
    __nv_bfloat16 l2 = __float2bfloat16(v.z - __bfloat162float(h2));
    __nv_bfloat16 l3 = __float2bfloat16(v.w - __bfloat162float(h3));
    uint2 ph, pl;
    ph.x = (uint32_t)__bfloat16_as_ushort(h0) | ((uint32_t)__bfloat16_as_ushort(h1) << 16);
    ph.y = (uint32_t)__bfloat16_as_ushort(h2) | ((uint32_t)__bfloat16_as_ushort(h3) << 16);
    pl.x = (uint32_t)__bfloat16_as_ushort(l0) | ((uint32_t)__bfloat16_as_ushort(l1) << 16);
    pl.y = (uint32_t)__bfloat16_as_ushort(l2) | ((uint32_t)__bfloat16_as_ushort(l3) << 16);
    *reinterpret_cast<uint2*>(g_ahi + (size_t)i * 4) = ph;
    *reinterpret_cast<uint2*>(g_alo + (size_t)i * 4) = pl;
}

__global__ void convw_kernel(int buf, const float* __restrict__ Wk, const float* __restrict__ Wq,
                             const float* __restrict__ Wv, const float* __restrict__ Ws) {
    int idx = blockIdx.x * blockDim.x + threadIdx.x;
    if (idx >= 4 * 16384) return;
    int m = idx >> 14, rem = idx & 16383, k = rem >> 7, n = rem & 127;
    const float* W = (m == 0) ? Wk : (m == 1) ? Wq : (m == 2) ? Wv : Ws;
    float v = W[k * 128 + n];
    __nv_bfloat16 h = __float2bfloat16(v);
    __nv_bfloat16 l = __float2bfloat16(v - __bfloat162float(h));
    size_t o = (size_t)buf * 65536 + m * 16384 + n * 128 + k;   // transposed [n][k]
    g_bthi[o] = h;
    g_btlo[o] = l;
}

// ---------------- HMMA bf16 hi/lo split GEMM ----------------
// grid = (NTILES, 4): blockIdx.y = which weight matrix (k,q,v,s).
// Outputs: k -> g_ks[:,0:128], s -> g_ks[:,128:256] (fp32),
//          q (prehalved), v -> g_qvh interleaved ([q4|v4] 16B groups, fp16).
#define SM_AH 0
#define SM_AL 32768
#define SM_BH 65536
#define SM_BL 98304
#define SM_TOTAL 131072

__global__ void __launch_bounds__(256, 1) mma_kernel(int buf, const float* __restrict__ bias) {
    extern __shared__ char sm[];
    uint32_t sb = smem_u32(sm);
    const int tid = threadIdx.x, wid = tid >> 5, lane = tid & 31;
    const int mat = blockIdx.y;
    const int row0 = blockIdx.x * 128;

    const __nv_bfloat16* Bh_g = g_bthi + (size_t)buf * 65536 + (size_t)mat * 16384;
    const __nv_bfloat16* Bl_g = g_btlo + (size_t)buf * 65536 + (size_t)mat * 16384;
#pragma unroll
    for (int p = 0; p < 8; p++) {
        int c = tid + p * 256;            // 0..2047
        int r = c >> 4, ch = c & 15;
        uint32_t so = swz(r, ch);
        int gr = row0 + r;
        uint4 vh = make_uint4(0, 0, 0, 0), vl = make_uint4(0, 0, 0, 0);
        if (gr < N_NODES) {
            vh = *reinterpret_cast<const uint4*>(g_ahi + (size_t)gr * DF + ch * 8);
            vl = *reinterpret_cast<const uint4*>(g_alo + (size_t)gr * DF + ch * 8);
        }
        *reinterpret_cast<uint4*>(sm + SM_AH + so) = vh;
        *reinterpret_cast<uint4*>(sm + SM_AL + so) = vl;
        *reinterpret_cast<uint4*>(sm + SM_BH + so) =
            *reinterpret_cast<const uint4*>(Bh_g + (size_t)r * 128 + ch * 8);
        *reinterpret_cast<uint4*>(sm + SM_BL + so) =
            *reinterpret_cast<const uint4*>(Bl_g + (size_t)r * 128 + ch * 8);
    }
    __syncthreads();

    const int wm = (wid & 1) * 64;
    const int wn = (wid >> 1) * 32;

    float acc[4][4][4];
#pragma unroll
    for (int i = 0; i < 4; i++)
#pragma unroll
        for (int j = 0; j < 4; j++)
#pragma unroll
            for (int e = 0; e < 4; e++) acc[i][j][e] = 0.f;

    const int a_sel = lane >> 3;
    const int a_row = (lane & 7) + (a_sel & 1) * 8;
    const int a_chk = a_sel >> 1;
    const int b_l   = lane & 15;
    const int b_row = b_l & 7;
    const int b_chk = b_l >> 3;

#pragma unroll
    for (int pass = 0; pass < 3; pass++) {
        uint32_t abase = sb + ((pass == 1) ? SM_AL : SM_AH);
        uint32_t bbase = sb + ((pass == 2) ? SM_BL : SM_BH);
#pragma unroll
        for (int k0 = 0; k0 < 128; k0 += 16) {
            int kc = k0 >> 3;
            uint32_t a[4][4], b[4][2];
#pragma unroll
            for (int mt = 0; mt < 4; mt++) {
                int row = wm + mt * 16 + a_row;
                LDSM_X4(a[mt][0], a[mt][1], a[mt][2], a[mt][3], abase + swz(row, kc + a_chk));
            }
#pragma unroll
            for (int nt = 0; nt < 4; nt++) {
                int row = wn + nt * 8 + b_row;
                LDSM_X2(b[nt][0], b[nt][1], bbase + swz(row, kc + b_chk));
            }
#pragma unroll
            for (int mt = 0; mt < 4; mt++)
#pragma unroll
                for (int nt = 0; nt < 4; nt++)
                    MMA16816(acc[mt][nt], a[mt], b[nt]);
        }
    }

    // epilogue
    const int gq = lane >> 2, tq = lane & 3;
    const bool is_qv = (mat == 1) || (mat == 2);
    const float qscale = (mat == 1) ? 0.5f : 1.f;   // q stored pre-halved
    float* OutF = (mat == 0) ? g_ks : (g_ks + 128); // k or s
#pragma unroll
    for (int mt = 0; mt < 4; mt++) {
#pragma unroll
        for (int nt = 0; nt < 4; nt++) {
            int col = wn + nt * 8 + tq * 2;
            int r0 = row0 + wm + mt * 16 + gq;
            if (is_qv) {
                int off = ((col >> 2) << 3) + (col & 3) + ((mat == 2) ? 4 : 0);
                if (r0 < N_NODES) {
                    __half2 h = __floats2half2_rn(acc[mt][nt][0] * qscale, acc[mt][nt][1] * qscale);
                    *reinterpret_cast<__half2*>(g_qvh + (size_t)r0 * 256 + off) = h;
                }
                if (r0 + 8 < N_NODES) {
                    __half2 h = __floats2half2_rn(acc[mt][nt][2] * qscale, acc[mt][nt][3] * qscale);
                    *reinterpret_cast<__half2*>(g_qvh + (size_t)(r0 + 8) * 256 + off) = h;
                }
            } else {
                float bx = 0.f, by = 0.f;
                if (mat == 3) { bx = bias[col]; by = bias[col + 1]; }
                if (r0 < N_NODES) {
                    float2 v = make_float2(acc[mt][nt][0] + bx, acc[mt][nt][1] + by);
                    *reinterpret_cast<float2*>(OutF + (size_t)r0 * 256 + col) = v;
                }
                if (r0 + 8 < N_NODES) {
                    float2 v = make_float2(acc[mt][nt][2] + bx, acc[mt][nt][3] + by);
                    *reinterpret_cast<float2*>(OutF + (size_t)(r0 + 8) * 256 + col) = v;
                }
            }
        }
    }
}

// ---------------- edge aggregation: one warp per destination node ----------------
// Interleaved fp16 [q/2|v] rows, ONE uint4 load per edge-lane, unroll 8 for MLP.
// kk is pre-halved once per node; gate input = k/2 + q/2 feeds tanh directly.
__device__ __forceinline__ void gate4(float4& acc, const float4 kk2, uint4 qv) {
    float2 q01 = __half22float2(*reinterpret_cast<__half2*>(&qv.x));
    float2 q23 = __half22float2(*reinterpret_cast<__half2*>(&qv.y));
    float2 v01 = __half22float2(*reinterpret_cast<__half2*>(&qv.z));
    float2 v23 = __half22float2(*reinterpret_cast<__half2*>(&qv.w));
    acc.x = fmaf(fsig_h(kk2.x + q01.x), v01.x, acc.x);
    acc.y = fmaf(fsig_h(kk2.y + q01.y), v01.y, acc.y);
    acc.z = fmaf(fsig_h(kk2.z + q23.x), v23.x, acc.z);
    acc.w = fmaf(fsig_h(kk2.w + q23.y), v23.y, acc.w);
}

__global__ void __launch_bounds__(256) agg_kernel(int split_out,
        const float* __restrict__ Wk3, const float* __restrict__ Wq3,
        const float* __restrict__ Wv3, const float* __restrict__ Ws3,
        const float* __restrict__ b3) {
    int gw = (blockIdx.x * blockDim.x + threadIdx.x) >> 5;
    if (gw >= N_NODES) return;
    int lane = threadIdx.x & 31;
    int lane4 = lane * 4;
    int lane8 = lane * 8;

    const float* ks_row = g_ks + (size_t)gw * 256;
    float4 kk = *reinterpret_cast<const float4*>(ks_row + lane4);
    float4 kk2 = make_float4(kk.x * 0.5f, kk.y * 0.5f, kk.z * 0.5f, kk.w * 0.5f);
    float4 a0 = make_float4(0.f, 0.f, 0.f, 0.f);
    float4 a1 = make_float4(0.f, 0.f, 0.f, 0.f);

    int j = g_rowptr[gw], end = g_rowptr[gw + 1];
    for (; j + 8 <= end; j += 8) {
        int s0 = g_esrc[j + 0], s1 = g_esrc[j + 1], s2 = g_esrc[j + 2], s3 = g_esrc[j + 3];
        int s4 = g_esrc[j + 4], s5 = g_esrc[j + 5], s6 = g_esrc[j + 6], s7 = g_esrc[j + 7];
        uint4 t0 = *reinterpret_cast<const uint4*>(g_qvh + (size_t)s0 * 256 + lane8);
        uint4 t1 = *reinterpret_cast<const uint4*>(g_qvh + (size_t)s1 * 256 + lane8);
        uint4 t2 = *reinterpret_cast<const uint4*>(g_qvh + (size_t)s2 * 256 + lane8);
        uint4 t3 = *reinterpret_cast<const uint4*>(g_qvh + (size_t)s3 * 256 + lane8);
        uint4 t4 = *reinterpret_cast<const uint4*>(g_qvh + (size_t)s4 * 256 + lane8);
        uint4 t5 = *reinterpret_cast<const uint4*>(g_qvh + (size_t)s5 * 256 + lane8);
        uint4 t6 = *reinterpret_cast<const uint4*>(g_qvh + (size_t)s6 * 256 + lane8);
        uint4 t7 = *reinterpret_cast<const uint4*>(g_qvh + (size_t)s7 * 256 + lane8);
        gate4(a0, kk2, t0); gate4(a1, kk2, t1);
        gate4(a0, kk2, t2); gate4(a1, kk2, t3);
        gate4(a0, kk2, t4); gate4(a1, kk2, t5);
        gate4(a0, kk2, t6); gate4(a1, kk2, t7);
    }
    if (j + 4 <= end) {
        int s0 = g_esrc[j + 0], s1 = g_esrc[j + 1], s2 = g_esrc[j + 2], s3 = g_esrc[j + 3];
        uint4 t0 = *reinterpret_cast<const uint4*>(g_qvh + (size_t)s0 * 256 + lane8);
        uint4 t1 = *reinterpret_cast<const uint4*>(g_qvh + (size_t)s1 * 256 + lane8);
        uint4 t2 = *reinterpret_cast<const uint4*>(g_qvh + (size_t)s2 * 256 + lane8);
        uint4 t3 = *reinterpret_cast<const uint4*>(g_qvh + (size_t)s3 * 256 + lane8);
        gate4(a0, kk2, t0); gate4(a1, kk2, t1);
        gate4(a0, kk2, t2); gate4(a1, kk2, t3);
        j += 4;
    }
    for (; j < end; j++) {
        uint4 t = *reinterpret_cast<const uint4*>(g_qvh + (size_t)g_esrc[j] * 256 + lane8);
        gate4(a0, kk2, t);
    }

    float4 ss = *reinterpret_cast<const float4*>(ks_row + 128 + lane4);
    float4 r = make_float4(fmaxf(a0.x + a1.x + ss.x, 0.f),
                           fmaxf(a0.y + a1.y + ss.y, 0.f),
                           fmaxf(a0.z + a1.z + ss.z, 0.f),
                           fmaxf(a0.w + a1.w + ss.w, 0.f));
    if (split_out) {
        size_t fo = (size_t)gw * DF + lane4;
        __nv_bfloat16 h0 = __float2bfloat16(r.x), h1 = __float2bfloat16(r.y);
        __nv_bfloat16 h2 = __float2bfloat16(r.z), h3 = __float2bfloat16(r.w);
        __nv_bfloat16 l0 = __float2bfloat16(r.x - __bfloat162float(h0));
        __nv_bfloat16 l1 = __float2bfloat16(r.y - __bfloat162float(h1));
        __nv_bfloat16 l2 = __float2bfloat16(r.z - __bfloat162float(h2));
        __nv_bfloat16 l3 = __float2bfloat16(r.w - __bfloat162float(h3));
        uint2 ph, pl;
        ph.x = (uint32_t)__bfloat16_as_ushort(h0) | ((uint32_t)__bfloat16_as_ushort(h1) << 16);
        ph.y = (uint32_t)__bfloat16_as_ushort(h2) | ((uint32_t)__bfloat16_as_ushort(h3) << 16);
        pl.x = (uint32_t)__bfloat16_as_ushort(l0) | ((uint32_t)__bfloat16_as_ushort(l1) << 16);
        pl.y = (uint32_t)__bfloat16_as_ushort(l2) | ((uint32_t)__bfloat16_as_ushort(l3) << 16);
        *reinterpret_cast<uint2*>(g_ahi + fo) = ph;
        *reinterpret_cast<uint2*>(g_alo + fo) = pl;
    } else {
        // fused layer-3 projections (D_OUT = 1)
        float4 wk = *reinterpret_cast<const float4*>(Wk3 + lane4);
        float4 wq = *reinterpret_cast<const float4*>(Wq3 + lane4);
        float4 wv = *reinterpret_cast<const float4*>(Wv3 + lane4);
        float4 ws = *reinterpret_cast<const float4*>(Ws3 + lane4);
        float pk = r.x * wk.x + r.y * wk.y + r.z * wk.z + r.w * wk.w;
        float pq = r.x * wq.x + r.y * wq.y + r.z * wq.z + r.w * wq.w;
        float pv = r.x * wv.x + r.y * wv.y + r.z * wv.z + r.w * wv.w;
        float ps = r.x * ws.x + r.y * ws.y + r.z * ws.z + r.w * ws.w;
#pragma unroll
        for (int o = 16; o; o >>= 1) {
            pk += __shfl_xor_sync(0xffffffffu, pk, o);
            pq += __shfl_xor_sync(0xffffffffu, pq, o);
            pv += __shfl_xor_sync(0xffffffffu, pv, o);
            ps += __shfl_xor_sync(0xffffffffu, ps, o);
        }
        if (lane == 0) {
            g3k[gw] = pk; g3q[gw] = pq; g3v[gw] = pv; g3s[gw] = ps + b3[0];
        }
    }
}

// ---------------- layer 3 edge aggregation (exact sigmoid) ----------------
__global__ void agg3_kernel(float* __restrict__ out) {
    int i = blockIdx.x * blockDim.x + threadIdx.x;
    if (i >= N_NODES) return;
    float ki = g3k[i];
    float acc = 0.f;
    int end = g_rowptr[i + 1];
    for (int j = g_rowptr[i]; j < end; j++) {
        int s = g_esrc[j];
        acc += fsig(ki + g3q[s]) * g3v[s];
    }
    out[i] = acc + g3s[i];
}

// ---------------- launch ----------------
extern "C" void kernel_launch(void* const* d_in, const int* in_sizes, int n_in,
                              void* d_out, int out_size) {
    const float* x   = (const float*)d_in[0];
    const int*   ei  = (const int*)d_in[1];
    const int*   src = ei;
    const int*   dst = ei + N_EDGES;
    const float* Wk1 = (const float*)d_in[2];
    const float* Wq1 = (const float*)d_in[3];
    const float* Wv1 = (const float*)d_in[4];
    const float* Ws1 = (const float*)d_in[5];
    const float* b1  = (const float*)d_in[6];
    const float* Wk2 = (const float*)d_in[7];
    const float* Wq2 = (const float*)d_in[8];
    const float* Wv2 = (const float*)d_in[9];
    const float* Ws2 = (const float*)d_in[10];
    const float* b2  = (const float*)d_in[11];
    const float* Wk3 = (const float*)d_in[12];
    const float* Wq3 = (const float*)d_in[13];
    const float* Wv3 = (const float*)d_in[14];
    const float* Ws3 = (const float*)d_in[15];
    const float* b3  = (const float*)d_in[16];
    float* out = (float*)d_out;

    cudaFuncSetAttribute(mma_kernel, cudaFuncAttributeMaxDynamicSharedMemorySize, SM_TOTAL);

    int nblk = (N_NODES + 255) / 256;
    int eblk = (N_EDGES + 255) / 256;
    dim3 mgrid(NTILES, 4);
    int  conv_blocks = ((N_NODES * DF) / 4 + 255) / 256;
    int  agg_blocks  = (N_NODES * 32 + 255) / 256;

    // Side stream: both weight conversions + CSR build, overlapped with the
    // main-stream conv/GEMM chain.
    cudaStream_t s1;
    cudaStreamCreateWithFlags(&s1, cudaStreamNonBlocking);
    cudaEvent_t eFork, eW, eJoin;
    cudaEventCreateWithFlags(&eFork, cudaEventDisableTiming);
    cudaEventCreateWithFlags(&eW, cudaEventDisableTiming);
    cudaEventCreateWithFlags(&eJoin, cudaEventDisableTiming);

    cudaEventRecord(eFork, 0);
    cudaStreamWaitEvent(s1, eFork, 0);
    convw_kernel<<<256, 256, 0, s1>>>(0, Wk1, Wq1, Wv1, Ws1);
    convw_kernel<<<256, 256, 0, s1>>>(1, Wk2, Wq2, Wv2, Ws2);
    cudaEventRecord(eW, s1);
    zero_cnt_kernel<<<nblk, 256, 0, s1>>>();
    hist_kernel<<<eblk, 256, 0, s1>>>(dst);
    scan_kernel<<<1, 1024, 0, s1>>>();
    scatter_kernel<<<eblk, 256, 0, s1>>>(src, dst);
    cudaEventRecord(eJoin, s1);

    // main stream: layer-1 conv + GEMM (concurrent with CSR)
    convx_kernel<<<conv_blocks, 256>>>(x);
    cudaStreamWaitEvent(0, eW, 0);
    mma_kernel<<<mgrid, 256, SM_TOTAL>>>(0, b1);

    // join: aggregation needs CSR + GEMM outputs
    cudaStreamWaitEvent(0, eJoin, 0);
    agg_kernel<<<agg_blocks, 256>>>(1, nullptr, nullptr, nullptr, nullptr, nullptr);
    // layer 2 (+fused layer-3 projections in the agg epilogue)
    mma_kernel<<<mgrid, 256, SM_TOTAL>>>(1, b2);
    agg_kernel<<<agg_blocks, 256>>>(0, Wk3, Wq3, Wv3, Ws3, b3);
    // layer 3 edge aggregation
    agg3_kernel<<<nblk, 256>>>(out);

    cudaEventDestroy(eFork);
    cudaEventDestroy(eW);
    cudaEventDestroy(eJoin);
    cudaStreamDestroy(s1);
}

// round 15
// speedup vs baseline: 1.1664x; 1.1664x over previous
#include <cuda_runtime.h>
#include <cuda_bf16.h>
#include <cuda_fp16.h>
#include <cstdint>

#define N_NODES 100000
#define N_EDGES 1600000
#define DF      128
#define NTILES  782          // ceil(100000/128)

// ---------------- scratch (device globals: allocation-free) ----------------
// per-src row (fp16, interleaved): 32 groups of [q4 | v4] (8 halfs = 16B each).
// q values stored PRE-HALVED (q/2) so the tanh-sigmoid needs no multiply.
static __device__ __half g_qvh[(size_t)N_NODES * 256];
// per-dst row (fp32): [k(128) | s(128)]
static __device__ float g_ks[(size_t)N_NODES * 256];
static __device__ int   g_rowptr[N_NODES + 1];
static __device__ int   g_fill[N_NODES];
static __device__ int   g_esrc[N_EDGES];
// bf16 hi/lo split operands (weights double-buffered: [layer][mat][n][k])
static __device__ __nv_bfloat16 g_ahi[(size_t)N_NODES * DF];
static __device__ __nv_bfloat16 g_alo[(size_t)N_NODES * DF];
static __device__ __nv_bfloat16 g_bthi[2 * 4 * 128 * 128];
static __device__ __nv_bfloat16 g_btlo[2 * 4 * 128 * 128];
// layer-3 scalars
static __device__ float g3k[N_NODES], g3q[N_NODES], g3v[N_NODES], g3s[N_NODES];

// ---------------- helpers ----------------
__device__ __forceinline__ uint32_t smem_u32(const void* p) {
    uint32_t a;
    asm("{ .reg .u64 t; cvta.to.shared.u64 t, %1; cvt.u32.u64 %0, t; }" : "=r"(a) : "l"(p));
    return a;
}

// XOR swizzle: tile is [128 rows][128 bf16] = row stride 256B, 16 chunks of 16B.
__device__ __forceinline__ uint32_t swz(int row, int chunk) {
    return (uint32_t)(row * 256 + ((chunk ^ (row & 7)) << 4));
}

#define LDSM_X4(r0, r1, r2, r3, addr) \
    asm volatile("ldmatrix.sync.aligned.m8n8.x4.shared.b16 {%0,%1,%2,%3}, [%4];" \
        : "=r"(r0), "=r"(r1), "=r"(r2), "=r"(r3) : "r"(addr))
#define LDSM_X2(r0, r1, addr) \
    asm volatile("ldmatrix.sync.aligned.m8n8.x2.shared.b16 {%0,%1}, [%2];" \
        : "=r"(r0), "=r"(r1) : "r"(addr))
#define MMA16816(d, a, b) \
    asm volatile("mma.sync.aligned.m16n8k16.row.col.f32.bf16.bf16.f32 " \
        "{%0,%1,%2,%3},{%4,%5,%6,%7},{%8,%9},{%0,%1,%2,%3};" \
        : "+f"((d)[0]), "+f"((d)[1]), "+f"((d)[2]), "+f"((d)[3]) \
        : "r"((a)[0]), "r"((a)[1]), "r"((a)[2]), "r"((a)[3]), "r"((b)[0]), "r"((b)[1]))

// exact sigmoid (final layer only)
__device__ __forceinline__ float fsig(float x) {
    return __fdividef(1.f, 1.f + __expf(-x));
}
// half-argument fast sigmoid: input y = x/2 already; sigma(x) = 0.5*tanh(y)+0.5
__device__ __forceinline__ float fsig_h(float y) {
    float t;
    asm("tanh.approx.f32 %0, %1;" : "=f"(t) : "f"(y));
    return fmaf(t, 0.5f, 0.5f);
}

// ---------------- CSR build ----------------
__global__ void zero_cnt_kernel() {
    int i = blockIdx.x * blockDim.x + threadIdx.x;
    if (i < N_NODES) g_fill[i] = 0;
}
__global__ void hist_kernel(const int* __restrict__ dst) {
    int e = blockIdx.x * blockDim.x + threadIdx.x;
    if (e < N_EDGES) atomicAdd(&g_fill[dst[e]], 1);
}
__global__ void scan_kernel() {
    __shared__ int wsum[32];
    __shared__ int carry;
    int tid = threadIdx.x, lane = tid & 31, wid = tid >> 5;
    if (tid == 0) carry = 0;
    __syncthreads();
    for (int base = 0; base < N_NODES; base += 4096) {
        int idx = base + tid * 4;
        int v0 = 0, v1 = 0, v2 = 0, v3 = 0;
        if (idx + 3 < N_NODES) {
            int4 t = *reinterpret_cast<const int4*>(g_fill + idx);
            v0 = t.x; v1 = t.y; v2 = t.z; v3 = t.w;
        } else {
            if (idx + 0 < N_NODES) v0 = g_fill[idx + 0];
            if (idx + 1 < N_NODES) v1 = g_fill[idx + 1];
            if (idx + 2 < N_NODES) v2 = g_fill[idx + 2];
            if (idx + 3 < N_NODES) v3 = g_fill[idx + 3];
        }
        int s0 = v0, s1 = s0 + v1, s2 = s1 + v2, s3 = s2 + v3;
        int x = s3;
#pragma unroll
        for (int o = 1; o < 32; o <<= 1) { int t = __shfl_up_sync(~0u, x, o); if (lane >= o) x += t; }
        if (lane == 31) wsum[wid] = x;
        __syncthreads();
        if (wid == 0) {
            int y = wsum[lane];
#pragma unroll
            for (int o = 1; o < 32; o <<= 1) { int t = __shfl_up_sync(~0u, y, o); if (lane >= o) y += t; }
            wsum[lane] = y;
        }
        __syncthreads();
        int excl = carry + (x - s3) + (wid ? wsum[wid - 1] : 0);
        int e0 = excl, e1 = excl + s0, e2 = excl + s1, e3 = excl + s2;
        if (idx + 0 < N_NODES) { g_rowptr[idx + 0] = e0; g_fill[idx + 0] = e0; }
        if (idx + 1 < N_NODES) { g_rowptr[idx + 1] = e1; g_fill[idx + 1] = e1; }
        if (idx + 2 < N_NODES) { g_rowptr[idx + 2] = e2; g_fill[idx + 2] = e2; }
        if (idx + 3 < N_NODES) { g_rowptr[idx + 3] = e3; g_fill[idx + 3] = e3; }
        __syncthreads();
        if (tid == 0) carry += wsum[31];
        __syncthreads();
    }
    if (tid == 0) g_rowptr[N_NODES] = N_EDGES;
}
__global__ void scatter_kernel(const int* __restrict__ src, const int* __restrict__ dst) {
    int e = blockIdx.x * blockDim.x + threadIdx.x;
    if (e < N_EDGES) {
        int d = dst[e];
        int p = atomicAdd(&g_fill[d], 1);
        g_esrc[p] = src[e];
    }
}

// ---------------- fp32 -> bf16 hi/lo conversion (layer-1 input only) ----------
__global__ void convx_kernel(const float* __restrict__ X) {
    int i = blockIdx.x * blockDim.x + threadIdx.x;
    if (i >= (N_NODES * DF) / 4) return;
    float4 v = *reinterpret_cast<const float4*>(X + (size_t)i * 4);
    __nv_bfloat16 h0 = __float2bfloat16(v.x), h1 = __float2bfloat16(v.y);
    __nv_bfloat16 h2 = __float2bfloat16(v.z), h3 = __float2bfloat16(v.w);
    __nv_bfloat16 l0 = __float2bfloat16(v.x - __bfloat162float(h0));
    __nv_bfloat16 l1 = __float2bfloat16(v.y - __bfloat162float(h1));
    __nv_bfloat16 l2 = __float2bfloat16(v.z - __bfloat162float(h2));
    __nv_bfloat16 l3 = __float2bfloat16(v.w - __bfloat162float(h3));
    uint2 ph, pl;
    ph.x = (uint32_t)__bfloat16_as_ushort(h0) | ((uint32_t)__bfloat16_as_ushort(h1) << 16);
    ph.y = (uint32_t)__bfloat16_as_ushort(h2) | ((uint32_t)__bfloat16_as_ushort(h3) << 16);
    pl.x = (uint32_t)__bfloat16_as_ushort(l0) | ((uint32_t)__bfloat16_as_ushort(l1) << 16);
    pl.y = (uint32_t)__bfloat16_as_ushort(l2) | ((uint32_t)__bfloat16_as_ushort(l3) << 16);
    *reinterpret_cast<uint2*>(g_ahi + (size_t)i * 4) = ph;
    *reinterpret_cast<uint2*>(g_alo + (size_t)i * 4) = pl;
}

__global__ void convw_kernel(int buf, const float* __restrict__ Wk, const float* __restrict__ Wq,
                             const float* __restrict__ Wv, const float* __restrict__ Ws) {
    int idx = blockIdx.x * blockDim.x + threadIdx.x;
    if (idx >= 4 * 16384) return;
    int m = idx >> 14, rem = idx & 16383, k = rem >> 7, n = rem & 127;
    const float* W = (m == 0) ? Wk : (m == 1) ? Wq : (m == 2) ? Wv : Ws;
    float v = W[k * 128 + n];
    __nv_bfloat16 h = __float2bfloat16(v);
    __nv_bfloat16 l = __float2bfloat16(v - __bfloat162float(h));
    size_t o = (size_t)buf * 65536 + m * 16384 + n * 128 + k;   // transposed [n][k]
    g_bthi[o] = h;
    g_btlo[o] = l;
}

// ---------------- HMMA bf16 hi/lo split GEMM ----------------
// grid = (NTILES, 4): blockIdx.y = which weight matrix (k,q,v,s).
// Outputs: k -> g_ks[:,0:128], s -> g_ks[:,128:256] (fp32),
//          q (prehalved), v -> g_qvh interleaved ([q4|v4] 16B groups, fp16).
#define SM_AH 0
#define SM_AL 32768
#define SM_BH 65536
#define SM_BL 98304
#define SM_TOTAL 131072

__global__ void __launch_bounds__(256, 1) mma_kernel(int buf, const float* __restrict__ bias) {
    extern __shared__ char sm[];
    uint32_t sb = smem_u32(sm);
    const int tid = threadIdx.x, wid = tid >> 5, lane = tid & 31;
    const int mat = blockIdx.y;
    const int row0 = blockIdx.x * 128;

    const __nv_bfloat16* Bh_g = g_bthi + (size_t)buf * 65536 + (size_t)mat * 16384;
    const __nv_bfloat16* Bl_g = g_btlo + (size_t)buf * 65536 + (size_t)mat * 16384;
#pragma unroll
    for (int p = 0; p < 8; p++) {
        int c = tid + p * 256;            // 0..2047
        int r = c >> 4, ch = c & 15;
        uint32_t so = swz(r, ch);
        int gr = row0 + r;
        uint4 vh = make_uint4(0, 0, 0, 0), vl = make_uint4(0, 0, 0, 0);
        if (gr < N_NODES) {
            vh = *reinterpret_cast<const uint4*>(g_ahi + (size_t)gr * DF + ch * 8);
            vl = *reinterpret_cast<const uint4*>(g_alo + (size_t)gr * DF + ch * 8);
        }
        *reinterpret_cast<uint4*>(sm + SM_AH + so) = vh;
        *reinterpret_cast<uint4*>(sm + SM_AL + so) = vl;
        *reinterpret_cast<uint4*>(sm + SM_BH + so) =
            *reinterpret_cast<const uint4*>(Bh_g + (size_t)r * 128 + ch * 8);
        *reinterpret_cast<uint4*>(sm + SM_BL + so) =
            *reinterpret_cast<const uint4*>(Bl_g + (size_t)r * 128 + ch * 8);
    }
    __syncthreads();

    const int wm = (wid & 1) * 64;
    const int wn = (wid >> 1) * 32;

    float acc[4][4][4];
#pragma unroll
    for (int i = 0; i < 4; i++)
#pragma unroll
        for (int j = 0; j < 4; j++)
#pragma unroll
            for (int e = 0; e < 4; e++) acc[i][j][e] = 0.f;

    const int a_sel = lane >> 3;
    const int a_row = (lane & 7) + (a_sel & 1) * 8;
    const int a_chk = a_sel >> 1;
    const int b_l   = lane & 15;
    const int b_row = b_l & 7;
    const int b_chk = b_l >> 3;

#pragma unroll
    for (int pass = 0; pass < 3; pass++) {
        uint32_t abase = sb + ((pass == 1) ? SM_AL : SM_AH);
        uint32_t bbase = sb + ((pass == 2) ? SM_BL : SM_BH);
#pragma unroll
        for (int k0 = 0; k0 < 128; k0 += 16) {
            int kc = k0 >> 3;
            uint32_t a[4][4], b[4][2];
#pragma unroll
            for (int mt = 0; mt < 4; mt++) {
                int row = wm + mt * 16 + a_row;
                LDSM_X4(a[mt][0], a[mt][1], a[mt][2], a[mt][3], abase + swz(row, kc + a_chk));
            }
#pragma unroll
            for (int nt = 0; nt < 4; nt++) {
                int row = wn + nt * 8 + b_row;
                LDSM_X2(b[nt][0], b[nt][1], bbase + swz(row, kc + b_chk));
            }
#pragma unroll
            for (int mt = 0; mt < 4; mt++)
#pragma unroll
                for (int nt = 0; nt < 4; nt++)
                    MMA16816(acc[mt][nt], a[mt], b[nt]);
        }
    }

    // epilogue
    const int gq = lane >> 2, tq = lane & 3;
    const bool is_qv = (mat == 1) || (mat == 2);
    const float qscale = (mat == 1) ? 0.5f : 1.f;   // q stored pre-halved
    float* OutF = (mat == 0) ? g_ks : (g_ks + 128); // k or s
#pragma unroll
    for (int mt = 0; mt < 4; mt++) {
#pragma unroll
        for (int nt = 0; nt < 4; nt++) {
            int col = wn + nt * 8 + tq * 2;
            int r0 = row0 + wm + mt * 16 + gq;
            if (is_qv) {
                int off = ((col >> 2) << 3) + (col & 3) + ((mat == 2) ? 4 : 0);
                if (r0 < N_NODES) {
                    __half2 h = __floats2half2_rn(acc[mt][nt][0] * qscale, acc[mt][nt][1] * qscale);
                    *reinterpret_cast<__half2*>(g_qvh + (size_t)r0 * 256 + off) = h;
                }
                if (r0 + 8 < N_NODES) {
                    __half2 h = __floats2half2_rn(acc[mt][nt][2] * qscale, acc[mt][nt][3] * qscale);
                    *reinterpret_cast<__half2*>(g_qvh + (size_t)(r0 + 8) * 256 + off) = h;
                }
            } else {
                float bx = 0.f, by = 0.f;
                if (mat == 3) { bx = bias[col]; by = bias[col + 1]; }
                if (r0 < N_NODES) {
                    float2 v = make_float2(acc[mt][nt][0] + bx, acc[mt][nt][1] + by);
                    *reinterpret_cast<float2*>(OutF + (size_t)r0 * 256 + col) = v;
                }
                if (r0 + 8 < N_NODES) {
                    float2 v = make_float2(acc[mt][nt][2] + bx, acc[mt][nt][3] + by);
                    *reinterpret_cast<float2*>(OutF + (size_t)(r0 + 8) * 256 + col) = v;
                }
            }
        }
    }
}

// ---------------- edge aggregation: one warp per destination node ----------------
// Interleaved fp16 [q/2|v] rows: ONE uint4 load per edge-lane, unroll 4.
__device__ __forceinline__ void gate4(float4& acc, const float4 kk2, uint4 qv) {
    float2 q01 = __half22float2(*reinterpret_cast<__half2*>(&qv.x));
    float2 q23 = __half22float2(*reinterpret_cast<__half2*>(&qv.y));
    float2 v01 = __half22float2(*reinterpret_cast<__half2*>(&qv.z));
    float2 v23 = __half22float2(*reinterpret_cast<__half2*>(&qv.w));
    acc.x = fmaf(fsig_h(kk2.x + q01.x), v01.x, acc.x);
    acc.y = fmaf(fsig_h(kk2.y + q01.y), v01.y, acc.y);
    acc.z = fmaf(fsig_h(kk2.z + q23.x), v23.x, acc.z);
    acc.w = fmaf(fsig_h(kk2.w + q23.y), v23.y, acc.w);
}

__global__ void __launch_bounds__(256) agg_kernel(int split_out,
        const float* __restrict__ Wk3, const float* __restrict__ Wq3,
        const float* __restrict__ Wv3, const float* __restrict__ Ws3,
        const float* __restrict__ b3) {
    int gw = (blockIdx.x * blockDim.x + threadIdx.x) >> 5;
    if (gw >= N_NODES) return;
    int lane = threadIdx.x & 31;
    int lane4 = lane * 4;
    int lane8 = lane * 8;   // interleaved qv: 8 halfs (16B) per lane

    const float* ks_row = g_ks + (size_t)gw * 256;
    float4 kk = *reinterpret_cast<const float4*>(ks_row + lane4);
    float4 kk2 = make_float4(kk.x * 0.5f, kk.y * 0.5f, kk.z * 0.5f, kk.w * 0.5f);
    float4 a0 = make_float4(0.f, 0.f, 0.f, 0.f);
    float4 a1 = make_float4(0.f, 0.f, 0.f, 0.f);

    int j = g_rowptr[gw], end = g_rowptr[gw + 1];
    for (; j + 4 <= end; j += 4) {
        int s0 = g_esrc[j], s1 = g_esrc[j + 1], s2 = g_esrc[j + 2], s3 = g_esrc[j + 3];
        uint4 t0 = *reinterpret_cast<const uint4*>(g_qvh + (size_t)s0 * 256 + lane8);
        uint4 t1 = *reinterpret_cast<const uint4*>(g_qvh + (size_t)s1 * 256 + lane8);
        uint4 t2 = *reinterpret_cast<const uint4*>(g_qvh + (size_t)s2 * 256 + lane8);
        uint4 t3 = *reinterpret_cast<const uint4*>(g_qvh + (size_t)s3 * 256 + lane8);
        gate4(a0, kk2, t0);
        gate4(a1, kk2, t1);
        gate4(a0, kk2, t2);
        gate4(a1, kk2, t3);
    }
    for (; j < end; j++) {
        uint4 t = *reinterpret_cast<const uint4*>(g_qvh + (size_t)g_esrc[j] * 256 + lane8);
        gate4(a0, kk2, t);
    }

    float4 ss = *reinterpret_cast<const float4*>(ks_row + 128 + lane4);
    float4 r = make_float4(fmaxf(a0.x + a1.x + ss.x, 0.f),
                           fmaxf(a0.y + a1.y + ss.y, 0.f),
                           fmaxf(a0.z + a1.z + ss.z, 0.f),
                           fmaxf(a0.w + a1.w + ss.w, 0.f));
    if (split_out) {
        size_t fo = (size_t)gw * DF + lane4;
        __nv_bfloat16 h0 = __float2bfloat16(r.x), h1 = __float2bfloat16(r.y);
        __nv_bfloat16 h2 = __float2bfloat16(r.z), h3 = __float2bfloat16(r.w);
        __nv_bfloat16 l0 = __float2bfloat16(r.x - __bfloat162float(h0));
        __nv_bfloat16 l1 = __float2bfloat16(r.y - __bfloat162float(h1));
        __nv_bfloat16 l2 = __float2bfloat16(r.z - __bfloat162float(h2));
        __nv_bfloat16 l3 = __float2bfloat16(r.w - __bfloat162float(h3));
        uint2 ph, pl;
        ph.x = (uint32_t)__bfloat16_as_ushort(h0) | ((uint32_t)__bfloat16_as_ushort(h1) << 16);
        ph.y = (uint32_t)__bfloat16_as_ushort(h2) | ((uint32_t)__bfloat16_as_ushort(h3) << 16);
        pl.x = (uint32_t)__bfloat16_as_ushort(l0) | ((uint32_t)__bfloat16_as_ushort(l1) << 16);
        pl.y = (uint32_t)__bfloat16_as_ushort(l2) | ((uint32_t)__bfloat16_as_ushort(l3) << 16);
        *reinterpret_cast<uint2*>(g_ahi + fo) = ph;
        *reinterpret_cast<uint2*>(g_alo + fo) = pl;
    } else {
        // fused layer-3 projections (D_OUT = 1)
        float4 wk = *reinterpret_cast<const float4*>(Wk3 + lane4);
        float4 wq = *reinterpret_cast<const float4*>(Wq3 + lane4);
        float4 wv = *reinterpret_cast<const float4*>(Wv3 + lane4);
        float4 ws = *reinterpret_cast<const float4*>(Ws3 + lane4);
        float pk = r.x * wk.x + r.y * wk.y + r.z * wk.z + r.w * wk.w;
        float pq = r.x * wq.x + r.y * wq.y + r.z * wq.z + r.w * wq.w;
        float pv = r.x * wv.x + r.y * wv.y + r.z * wv.z + r.w * wv.w;
        float ps = r.x * ws.x + r.y * ws.y + r.z * ws.z + r.w * ws.w;
#pragma unroll
        for (int o = 16; o; o >>= 1) {
            pk += __shfl_xor_sync(0xffffffffu, pk, o);
            pq += __shfl_xor_sync(0xffffffffu, pq, o);
            pv += __shfl_xor_sync(0xffffffffu, pv, o);
            ps += __shfl_xor_sync(0xffffffffu, ps, o);
        }
        if (lane == 0) {
            g3k[gw] = pk; g3q[gw] = pq; g3v[gw] = pv; g3s[gw] = ps + b3[0];
        }
    }
}

// ---------------- layer 3 edge aggregation (exact sigmoid) ----------------
__global__ void agg3_kernel(float* __restrict__ out) {
    int i = blockIdx.x * blockDim.x + threadIdx.x;
    if (i >= N_NODES) return;
    float ki = g3k[i];
    float acc = 0.f;
    int end = g_rowptr[i + 1];
    for (int j = g_rowptr[i]; j < end; j++) {
        int s = g_esrc[j];
        acc += fsig(ki + g3q[s]) * g3v[s];
    }
    out[i] = acc + g3s[i];
}

// ---------------- launch ----------------
extern "C" void kernel_launch(void* const* d_in, const int* in_sizes, int n_in,
                              void* d_out, int out_size) {
    const float* x   = (const float*)d_in[0];
    const int*   ei  = (const int*)d_in[1];
    const int*   src = ei;
    const int*   dst = ei + N_EDGES;
    const float* Wk1 = (const float*)d_in[2];
    const float* Wq1 = (const float*)d_in[3];
    const float* Wv1 = (const float*)d_in[4];
    const float* Ws1 = (const float*)d_in[5];
    const float* b1  = (const float*)d_in[6];
    const float* Wk2 = (const float*)d_in[7];
    const float* Wq2 = (const float*)d_in[8];
    const float* Wv2 = (const float*)d_in[9];
    const float* Ws2 = (const float*)d_in[10];
    const float* b2  = (const float*)d_in[11];
    const float* Wk3 = (const float*)d_in[12];
    const float* Wq3 = (const float*)d_in[13];
    const float* Wv3 = (const float*)d_in[14];
    const float* Ws3 = (const float*)d_in[15];
    const float* b3  = (const float*)d_in[16];
    float* out = (float*)d_out;

    cudaFuncSetAttribute(mma_kernel, cudaFuncAttributeMaxDynamicSharedMemorySize, SM_TOTAL);

    int nblk = (N_NODES + 255) / 256;
    int eblk = (N_EDGES + 255) / 256;
    dim3 mgrid(NTILES, 4);
    int  conv_blocks = ((N_NODES * DF) / 4 + 255) / 256;
    int  agg_blocks  = (N_NODES * 32 + 255) / 256;

    // Side stream: CSR build, then layer-2 weight conversion (never delays mma1).
    cudaStream_t s1;
    cudaStreamCreateWithFlags(&s1, cudaStreamNonBlocking);
    cudaEvent_t eFork, eJoin, eW2;
    cudaEventCreateWithFlags(&eFork, cudaEventDisableTiming);
    cudaEventCreateWithFlags(&eJoin, cudaEventDisableTiming);
    cudaEventCreateWithFlags(&eW2, cudaEventDisableTiming);

    cudaEventRecord(eFork, 0);
    cudaStreamWaitEvent(s1, eFork, 0);
    // CSR chain (side stream)
    zero_cnt_kernel<<<nblk, 256, 0, s1>>>();
    hist_kernel<<<eblk, 256, 0, s1>>>(dst);
    scan_kernel<<<1, 1024, 0, s1>>>();
    scatter_kernel<<<eblk, 256, 0, s1>>>(src, dst);
    cudaEventRecord(eJoin, s1);
    // layer-2 weights (side stream, off critical path)
    convw_kernel<<<256, 256, 0, s1>>>(1, Wk2, Wq2, Wv2, Ws2);
    cudaEventRecord(eW2, s1);

    // layer-1 GEMM chain (main stream, concurrent with CSR)
    convw_kernel<<<256, 256>>>(0, Wk1, Wq1, Wv1, Ws1);
    convx_kernel<<<conv_blocks, 256>>>(x);
    mma_kernel<<<mgrid, 256, SM_TOTAL>>>(0, b1);

    // join: aggregation needs both CSR and GEMM outputs
    cudaStreamWaitEvent(0, eJoin, 0);
    agg_kernel<<<agg_blocks, 256>>>(1, nullptr, nullptr, nullptr, nullptr, nullptr);
    // layer 2 (+fused layer-3 projections in the agg epilogue)
    cudaStreamWaitEvent(0, eW2, 0);
    mma_kernel<<<mgrid, 256, SM_TOTAL>>>(1, b2);
    agg_kernel<<<agg_blocks, 256>>>(0, Wk3, Wq3, Wv3, Ws3, b3);
    // layer 3 edge aggregation
    agg3_kernel<<<nblk, 256>>>(out);

    cudaEventDestroy(eFork);
    cudaEventDestroy(eJoin);
    cudaEventDestroy(eW2);
    cudaStreamDestroy(s1);
}